// round 5
// baseline (speedup 1.0000x reference)
#include <cuda_runtime.h>
#include <cuda_bf16.h>
#include <mma.h>
#include <cstdint>

using namespace nvcuda;
using bf16 = __nv_bfloat16;
#define DEV __device__ __forceinline__

static constexpr int NN = 8192;   // nodes
static constexpr int FI = 256;    // in features
static constexpr int FO = 256;    // out features
static constexpr int KW = 512;    // split-W contraction dim (W_hi | W_lo)

// GEMM tiling: CTA 64(m) x 128(n), 8 warps of 32x32, KC=64, 3 stages
static constexpr int TM   = 64;
static constexpr int TN   = 128;
static constexpr int KC   = 64;                   // K elems per stage
static constexpr int SROW = 72;                   // padded smem row = 144 B (conflict-free)
static constexpr int TA_B = TM * SROW * 2;        // A tile bytes  (9216)
static constexpr int TB_B = TN * SROW * 2;        // B tile bytes  (18432)
static constexpr int STAGE_B = TA_B + TB_B;       // 27648
static constexpr int S = 3;
static constexpr int SMEM_SZ = S * STAGE_B;       // 82944 -> 2 CTAs/SM
static constexpr int EROW = 132;                  // epilogue fp32 row stride

// ---------------- scratch (device globals; no runtime allocation) -----------
__device__ float g_dis[NN];
__device__ bf16  g_Abf[(size_t)NN * NN];     // bf16(A + I)
__device__ bf16  g_X2[(size_t)NN * KW];      // [ d^-1/2 X | d^-1/2 X ]
__device__ bf16  g_W2[(size_t)FO * KW];      // [ W_hi | W_lo ]
__device__ bf16  g_Pt[(size_t)FO * NN];      // Pt[f][j]
__device__ float g_C[2][(size_t)NN * FO];    // split-K partials

// ---------------- helpers ----------------
DEV uint32_t smem_u32(const void* p) {
    uint32_t a;
    asm("{ .reg .u64 t; cvta.to.shared.u64 t, %1; cvt.u32.u64 %0, t; }" : "=r"(a) : "l"(p));
    return a;
}
DEV void cp16(uint32_t s, const void* g) {
    asm volatile("cp.async.cg.shared.global [%0], [%1], 16;" :: "r"(s), "l"(g));
}
DEV void cp_commit() { asm volatile("cp.async.commit_group;" ::: "memory"); }

// ========================== prep: deg + bf16(A+I) ==========================
__global__ void __launch_bounds__(256) k_prep(const float* __restrict__ A) {
    const int row = blockIdx.x;
    const float4* A4 = reinterpret_cast<const float4*>(A + (size_t)row * NN);
    uint2* O = reinterpret_cast<uint2*>(g_Abf + (size_t)row * NN);

    float sum = 0.f;
#pragma unroll
    for (int u = 0; u < 8; u++) {
        const int p4 = threadIdx.x + u * 256;
        float4 v = A4[p4];
        const int d = row - p4 * 4;
        if (d >= 0 && d < 4) {                   // add identity before quantizing
            if      (d == 0) v.x += 1.f;
            else if (d == 1) v.y += 1.f;
            else if (d == 2) v.z += 1.f;
            else             v.w += 1.f;
        }
        sum += (v.x + v.y) + (v.z + v.w);
        __nv_bfloat162 lo = __floats2bfloat162_rn(v.x, v.y);
        __nv_bfloat162 hi = __floats2bfloat162_rn(v.z, v.w);
        uint2 st;
        st.x = *reinterpret_cast<uint32_t*>(&lo);
        st.y = *reinterpret_cast<uint32_t*>(&hi);
        O[p4] = st;
    }
    __shared__ float red[256];
    red[threadIdx.x] = sum;
    __syncthreads();
#pragma unroll
    for (int off = 128; off > 0; off >>= 1) {
        if (threadIdx.x < off) red[threadIdx.x] += red[threadIdx.x + off];
        __syncthreads();
    }
    if (threadIdx.x == 0) g_dis[row] = rsqrtf(red[0]);
}

// ================ quant: X2 = [ds*X | ds*X], W2 = [W_hi | W_lo] ============
__global__ void __launch_bounds__(256) k_x2(const float* __restrict__ X) {
    const int row = blockIdx.x, c = threadIdx.x;
    const float s = g_dis[row];
    const bf16 v = __float2bfloat16(s * X[(size_t)row * FI + c]);
    g_X2[(size_t)row * KW + c]      = v;
    g_X2[(size_t)row * KW + FI + c] = v;
}
__global__ void __launch_bounds__(256) k_w2(const float* __restrict__ W) {
    const int f = blockIdx.x, c = threadIdx.x;
    const float w = W[(size_t)f * FI + c];
    const bf16 hi = __float2bfloat16(w);
    const bf16 lo = __float2bfloat16(w - __bfloat162float(hi));
    g_W2[(size_t)f * KW + c]      = hi;
    g_W2[(size_t)f * KW + FI + c] = lo;
}

// ====================== combine: out = dis*(C0+C1) + b =====================
__global__ void __launch_bounds__(256) k_comb(float* __restrict__ out,
                                              const float* __restrict__ bias) {
    const int i = blockIdx.x, f = threadIdx.x;
    const size_t idx = (size_t)i * FO + f;
    out[idx] = g_dis[i] * (g_C[0][idx] + g_C[1][idx]) + bias[f];
}

// ========================== wmma bf16 GEMM =================================
// acc[m0+m, n0+n] = sum_k Aop[m0+m, k+koff] * Bop[n0+n, k+koff]
// mode 0: outB = bf16(acc);  mode 1: outF = acc (fp32 raw partial)
template <int ROWS>
DEV void load_tile(uint32_t sdst, const bf16* __restrict__ g, int row0,
                   int ktot, int k0) {
#pragma unroll
    for (int t = 0; t < ROWS * 8 / 256; t++) {
        const int c = threadIdx.x + t * 256;          // chunks of 16 B
        const int row = c >> 3, off = (c & 7) * 16;
        const uint32_t s = sdst + (uint32_t)(row * (SROW * 2) + off);
        const char* src =
            reinterpret_cast<const char*>(g + (size_t)(row0 + row) * ktot + k0) + off;
        cp16(s, src);
    }
}

__global__ void __launch_bounds__(256, 2)
k_gemm(const bf16* __restrict__ Ao, const bf16* __restrict__ Bo,
       int ktot, int nk, float* __restrict__ outF, bf16* __restrict__ outB,
       int ldo, int mode)
{
    extern __shared__ char smem[];
    const uint32_t sb = smem_u32(smem);
    const int wid = threadIdx.x >> 5;
    const int wm = wid & 1, wn = wid >> 1;            // 2x4 warp grid of 32x32
    const int m0 = blockIdx.x * TM, n0 = blockIdx.y * TN;
    const int koff = blockIdx.z * nk * KC;
    if (mode == 1) outF += (size_t)blockIdx.z * NN * FO;

    wmma::fragment<wmma::accumulator, 16, 16, 16, float> acc[2][2];
#pragma unroll
    for (int i = 0; i < 2; i++)
#pragma unroll
        for (int j = 0; j < 2; j++) wmma::fill_fragment(acc[i][j], 0.f);

    // prologue: stages 0,1
#pragma unroll
    for (int s = 0; s < S - 1; s++) {
        load_tile<TM>(sb + s * STAGE_B, Ao, m0, ktot, koff + s * KC);
        load_tile<TN>(sb + s * STAGE_B + TA_B, Bo, n0, ktot, koff + s * KC);
        cp_commit();
    }

    for (int k = 0; k < nk; k++) {
        asm volatile("cp.async.wait_group 1;" ::: "memory");   // stage k resident
        __syncthreads();   // stage (k+2)%S consumed by all; stage k visible

        if (k + 2 < nk) {
            const int s = (k + 2) % S;
            load_tile<TM>(sb + s * STAGE_B, Ao, m0, ktot, koff + (k + 2) * KC);
            load_tile<TN>(sb + s * STAGE_B + TA_B, Bo, n0, ktot, koff + (k + 2) * KC);
        }
        cp_commit();

        const bf16* sa  = reinterpret_cast<const bf16*>(smem + (k % S) * STAGE_B);
        const bf16* sbp = reinterpret_cast<const bf16*>(smem + (k % S) * STAGE_B + TA_B);
#pragma unroll
        for (int kk = 0; kk < KC / 16; kk++) {
            wmma::fragment<wmma::matrix_a, 16, 16, 16, bf16, wmma::row_major> fa[2];
            wmma::fragment<wmma::matrix_b, 16, 16, 16, bf16, wmma::col_major> fb[2];
#pragma unroll
            for (int i = 0; i < 2; i++)
                wmma::load_matrix_sync(fa[i], sa + (wm * 32 + i * 16) * SROW + kk * 16, SROW);
#pragma unroll
            for (int j = 0; j < 2; j++)
                wmma::load_matrix_sync(fb[j], sbp + (wn * 32 + j * 16) * SROW + kk * 16, SROW);
#pragma unroll
            for (int i = 0; i < 2; i++)
#pragma unroll
                for (int j = 0; j < 2; j++)
                    wmma::mma_sync(acc[i][j], fa[i], fb[j], acc[i][j]);
        }
    }

    // ------------- epilogue via smem roundtrip -------------
    __syncthreads();
    float* es = reinterpret_cast<float*>(smem);
#pragma unroll
    for (int i = 0; i < 2; i++)
#pragma unroll
        for (int j = 0; j < 2; j++)
            wmma::store_matrix_sync(es + (size_t)(wm * 32 + i * 16) * EROW + wn * 32 + j * 16,
                                    acc[i][j], EROW, wmma::mem_row_major);
    __syncthreads();

    const int tid = threadIdx.x;
    if (mode == 0) {
#pragma unroll
        for (int t = 0; t < 8; t++) {
            const int e = tid + t * 256;                 // groups of 4 elems
            const int row = e >> 5, c4 = (e & 31) * 4;
            const float* src = es + (size_t)row * EROW + c4;
            __nv_bfloat162 h0 = __floats2bfloat162_rn(src[0], src[1]);
            __nv_bfloat162 h1 = __floats2bfloat162_rn(src[2], src[3]);
            uint2 st;
            st.x = *reinterpret_cast<uint32_t*>(&h0);
            st.y = *reinterpret_cast<uint32_t*>(&h1);
            *reinterpret_cast<uint2*>(outB + (size_t)(m0 + row) * ldo + n0 + c4) = st;
        }
    } else {
#pragma unroll
        for (int t = 0; t < 8; t++) {
            const int e = tid + t * 256;
            const int row = e >> 5, c4 = (e & 31) * 4;
            const float* src = es + (size_t)row * EROW + c4;
            float4 v = { src[0], src[1], src[2], src[3] };
            *reinterpret_cast<float4*>(outF + (size_t)(m0 + row) * ldo + n0 + c4) = v;
        }
    }
}

// ================================ launch ===================================
extern "C" void kernel_launch(void* const* d_in, const int* in_sizes, int n_in,
                              void* d_out, int out_size) {
    const float* X = (const float*)d_in[0];
    const float* A = (const float*)d_in[1];
    const float* W = (const float*)d_in[2];
    const float* b = (const float*)d_in[3];
    float* out = (float*)d_out;

    cudaFuncSetAttribute(k_gemm, cudaFuncAttributeMaxDynamicSharedMemorySize, SMEM_SZ);

    bf16 *Abf, *X2, *W2, *Pt;
    float* Cs;
    cudaGetSymbolAddress((void**)&Abf, g_Abf);
    cudaGetSymbolAddress((void**)&X2,  g_X2);
    cudaGetSymbolAddress((void**)&W2,  g_W2);
    cudaGetSymbolAddress((void**)&Pt,  g_Pt);
    cudaGetSymbolAddress((void**)&Cs,  g_C);

    k_prep<<<NN, 256>>>(A);
    k_x2<<<NN, 256>>>(X);
    k_w2<<<FO, 256>>>(W);
    // GEMM1: Pt[f, j] = bf16( sum_k W2[f,k] * X2[j,k] )   M=FO, N=NN, K=KW
    k_gemm<<<dim3(FO / TM, NN / TN), 256, SMEM_SZ>>>(
        W2, X2, KW, KW / KC, nullptr, Pt, NN, 0);
    // GEMM2 (split-K=2): C[z][i,f] = sum_{j in half z} Abf[i,j] * Pt[f,j]
    k_gemm<<<dim3(NN / TM, FO / TN, 2), 256, SMEM_SZ>>>(
        Abf, Pt, NN, NN / KC / 2, Cs, nullptr, FO, 1);
    // out = dis * (C0 + C1) + b
    k_comb<<<NN, 256>>>(out, b);
}

// round 7
// speedup vs baseline: 1.1316x; 1.1316x over previous
#include <cuda_runtime.h>
#include <cuda_bf16.h>
#include <mma.h>
#include <cstdint>

using namespace nvcuda;
using bf16 = __nv_bfloat16;
#define DEV __device__ __forceinline__

static constexpr int NN = 8192;   // nodes
static constexpr int FI = 256;    // in features
static constexpr int FO = 256;    // out features
static constexpr int KW = 512;    // split-W contraction dim (W_hi | W_lo)

// GEMM tiling: CTA 128(m) x 256(n), 8 warps of 64x64, KC=64, 3 stages
static constexpr int TM   = 128;
static constexpr int TN   = 256;
static constexpr int KC   = 64;
static constexpr int SROW = 72;                   // padded smem row = 144 B
static constexpr int TA_B = TM * SROW * 2;        // 18432
static constexpr int TB_B = TN * SROW * 2;        // 36864
static constexpr int STAGE_B = TA_B + TB_B;       // 55296
static constexpr int S = 3;
static constexpr int SMEM_SZ = S * STAGE_B;       // 165888
static constexpr int ECOL = 136;  // mode-0 col-major ldm (mult of 4): es[m + f*ECOL]
static constexpr int EROW = 260;  // mode-1 row-major ldm (mult of 4)

// ---------------- scratch (device globals) ----------------
__device__ float g_dis[NN];
__device__ bf16  g_Abf[(size_t)NN * NN];     // bf16(A + I)
__device__ bf16  g_X2[(size_t)NN * KW];      // [ d^-1/2 X | d^-1/2 X ]
__device__ bf16  g_W2[(size_t)FO * KW];      // [ W_hi | W_lo ]
__device__ bf16  g_Pt[(size_t)FO * NN];      // Pt[f][j]
__device__ float g_C[2][(size_t)NN * FO];    // split-K partials

// ---------------- helpers ----------------
DEV uint32_t smem_u32(const void* p) {
    uint32_t a;
    asm("{ .reg .u64 t; cvta.to.shared.u64 t, %1; cvt.u32.u64 %0, t; }" : "=r"(a) : "l"(p));
    return a;
}
DEV void cp16(uint32_t s, const void* g) {
    asm volatile("cp.async.cg.shared.global [%0], [%1], 16;" :: "r"(s), "l"(g));
}
DEV void cp_commit() { asm volatile("cp.async.commit_group;" ::: "memory"); }

// ========================== prep: deg + bf16(A+I) ==========================
__global__ void __launch_bounds__(256) k_prep(const float* __restrict__ A) {
    const int row = blockIdx.x;
    const float4* A4 = reinterpret_cast<const float4*>(A + (size_t)row * NN);
    uint2* O = reinterpret_cast<uint2*>(g_Abf + (size_t)row * NN);

    float sum = 0.f;
#pragma unroll
    for (int u = 0; u < 8; u++) {
        const int p4 = threadIdx.x + u * 256;
        float4 v = A4[p4];
        const int d = row - p4 * 4;
        if (d >= 0 && d < 4) {
            if      (d == 0) v.x += 1.f;
            else if (d == 1) v.y += 1.f;
            else if (d == 2) v.z += 1.f;
            else             v.w += 1.f;
        }
        sum += (v.x + v.y) + (v.z + v.w);
        __nv_bfloat162 lo = __floats2bfloat162_rn(v.x, v.y);
        __nv_bfloat162 hi = __floats2bfloat162_rn(v.z, v.w);
        uint2 st;
        st.x = *reinterpret_cast<uint32_t*>(&lo);
        st.y = *reinterpret_cast<uint32_t*>(&hi);
        O[p4] = st;
    }
    __shared__ float red[256];
    red[threadIdx.x] = sum;
    __syncthreads();
#pragma unroll
    for (int off = 128; off > 0; off >>= 1) {
        if (threadIdx.x < off) red[threadIdx.x] += red[threadIdx.x + off];
        __syncthreads();
    }
    if (threadIdx.x == 0) g_dis[row] = rsqrtf(red[0]);
}

// ============== fused quant: X2 (grid < NN) and W2 (grid >= NN) ============
__global__ void __launch_bounds__(256) k_quant(const float* __restrict__ X,
                                               const float* __restrict__ W) {
    const int bid = blockIdx.x, c = threadIdx.x;
    if (bid < NN) {
        const float s = g_dis[bid];
        const bf16 v = __float2bfloat16(s * X[(size_t)bid * FI + c]);
        g_X2[(size_t)bid * KW + c]      = v;
        g_X2[(size_t)bid * KW + FI + c] = v;
    } else {
        const int f = bid - NN;
        const float w = W[(size_t)f * FI + c];
        const bf16 hi = __float2bfloat16(w);
        const bf16 lo = __float2bfloat16(w - __bfloat162float(hi));
        g_W2[(size_t)f * KW + c]      = hi;
        g_W2[(size_t)f * KW + FI + c] = lo;
    }
}

// ====================== combine: out = dis*(C0+C1) + b =====================
__global__ void __launch_bounds__(256) k_comb(float* __restrict__ out,
                                              const float* __restrict__ bias) {
    const int i = blockIdx.x, f = threadIdx.x;
    const size_t idx = (size_t)i * FO + f;
    out[idx] = g_dis[i] * (g_C[0][idx] + g_C[1][idx]) + bias[f];
}

// ========================== wmma bf16 GEMM =================================
// acc[m0+m, n] = sum_k Aop[m0+m, k+koff] * Bop[n, k+koff]   (n covers full TN)
// mode 0: Pt[n][m0+m] = bf16(acc)  (transpose write via col-major smem store)
// mode 1: outF[(m0+m)*FO + n] = acc (fp32 partial, per split-K slice)
template <int ROWS>
DEV void load_tile(uint32_t sdst, const bf16* __restrict__ g, int row0,
                   int ktot, int k0) {
#pragma unroll
    for (int t = 0; t < ROWS * 8 / 256; t++) {
        const int c = threadIdx.x + t * 256;          // 16B chunks
        const int row = c >> 3, off = (c & 7) * 16;
        const uint32_t s = sdst + (uint32_t)(row * (SROW * 2) + off);
        const char* src =
            reinterpret_cast<const char*>(g + (size_t)(row0 + row) * ktot + k0) + off;
        cp16(s, src);
    }
}

__global__ void __launch_bounds__(256, 1)
k_gemm(const bf16* __restrict__ Ao, const bf16* __restrict__ Bo,
       int ktot, int nk, float* __restrict__ outF, bf16* __restrict__ outB,
       int mode)
{
    extern __shared__ char smem[];
    const uint32_t sb = smem_u32(smem);
    const int wid = threadIdx.x >> 5, lid = threadIdx.x & 31;
    const int wm = wid & 1, wn = wid >> 1;            // 2x4 warp grid of 64x64
    const int m0 = blockIdx.x * TM;
    const int koff = blockIdx.z * nk * KC;
    if (mode == 1) outF += (size_t)blockIdx.z * NN * FO;

    wmma::fragment<wmma::accumulator, 16, 16, 16, float> acc[4][4];
#pragma unroll
    for (int i = 0; i < 4; i++)
#pragma unroll
        for (int j = 0; j < 4; j++) wmma::fill_fragment(acc[i][j], 0.f);

#pragma unroll
    for (int s = 0; s < S - 1; s++) {
        load_tile<TM>(sb + s * STAGE_B, Ao, m0, ktot, koff + s * KC);
        load_tile<TN>(sb + s * STAGE_B + TA_B, Bo, 0, ktot, koff + s * KC);
        cp_commit();
    }

    for (int k = 0; k < nk; k++) {
        asm volatile("cp.async.wait_group 1;" ::: "memory");
        __syncthreads();

        if (k + 2 < nk) {
            const int s = (k + 2) % S;
            load_tile<TM>(sb + s * STAGE_B, Ao, m0, ktot, koff + (k + 2) * KC);
            load_tile<TN>(sb + s * STAGE_B + TA_B, Bo, 0, ktot, koff + (k + 2) * KC);
        }
        cp_commit();

        const bf16* sa  = reinterpret_cast<const bf16*>(smem + (k % S) * STAGE_B);
        const bf16* sbp = reinterpret_cast<const bf16*>(smem + (k % S) * STAGE_B + TA_B);
#pragma unroll
        for (int kk = 0; kk < KC / 16; kk++) {
            wmma::fragment<wmma::matrix_a, 16, 16, 16, bf16, wmma::row_major> fa[4];
            wmma::fragment<wmma::matrix_b, 16, 16, 16, bf16, wmma::col_major> fb[4];
#pragma unroll
            for (int i = 0; i < 4; i++)
                wmma::load_matrix_sync(fa[i], sa + (wm * 64 + i * 16) * SROW + kk * 16, SROW);
#pragma unroll
            for (int j = 0; j < 4; j++)
                wmma::load_matrix_sync(fb[j], sbp + (wn * 64 + j * 16) * SROW + kk * 16, SROW);
#pragma unroll
            for (int i = 0; i < 4; i++)
#pragma unroll
                for (int j = 0; j < 4; j++)
                    wmma::mma_sync(acc[i][j], fa[i], fb[j], acc[i][j]);
        }
    }

    // ------------- epilogue via smem roundtrip -------------
    __syncthreads();
    float* es = reinterpret_cast<float*>(smem);

    if (mode == 0) {
        // col-major store: element (m, f) -> es[m + f*ECOL]  (transposed layout)
#pragma unroll
        for (int i = 0; i < 4; i++)
#pragma unroll
            for (int j = 0; j < 4; j++)
                wmma::store_matrix_sync(es + (wm * 64 + i * 16) +
                                            (size_t)(wn * 64 + j * 16) * ECOL,
                                        acc[i][j], ECOL, wmma::mem_col_major);
        __syncthreads();
        // Pt[f][m0+j]: warp wid owns f in [wid*32, wid*32+32); coalesced along j
#pragma unroll
        for (int ff = 0; ff < 32; ff++) {
            const int f = wid * 32 + ff;
            const float* base = es + (size_t)f * ECOL;
#pragma unroll
            for (int half = 0; half < 2; half++) {
                const int j = half * 64 + lid * 2;
                const float2 v = *reinterpret_cast<const float2*>(base + j);
                __nv_bfloat162 h = __floats2bfloat162_rn(v.x, v.y);
                *reinterpret_cast<uint32_t*>(outB + (size_t)f * NN + m0 + j) =
                    *reinterpret_cast<uint32_t*>(&h);
            }
        }
    } else {
#pragma unroll
        for (int i = 0; i < 4; i++)
#pragma unroll
            for (int j = 0; j < 4; j++)
                wmma::store_matrix_sync(es + (size_t)(wm * 64 + i * 16) * EROW +
                                            wn * 64 + j * 16,
                                        acc[i][j], EROW, wmma::mem_row_major);
        __syncthreads();
        const int tid = threadIdx.x;
#pragma unroll
        for (int t = 0; t < 32; t++) {
            const int e = tid + t * 256;                 // groups of 4 elems
            const int row = e >> 6, c4 = (e & 63) * 4;
            const float* src = es + (size_t)row * EROW + c4;
            float4 v = { src[0], src[1], src[2], src[3] };
            *reinterpret_cast<float4*>(outF + (size_t)(m0 + row) * FO + c4) = v;
        }
    }
}

// ================================ launch ===================================
extern "C" void kernel_launch(void* const* d_in, const int* in_sizes, int n_in,
                              void* d_out, int out_size) {
    const float* X = (const float*)d_in[0];
    const float* A = (const float*)d_in[1];
    const float* W = (const float*)d_in[2];
    const float* b = (const float*)d_in[3];
    float* out = (float*)d_out;

    cudaFuncSetAttribute(k_gemm, cudaFuncAttributeMaxDynamicSharedMemorySize, SMEM_SZ);

    bf16 *Abf, *X2, *W2, *Pt;
    float* Cs;
    cudaGetSymbolAddress((void**)&Abf, g_Abf);
    cudaGetSymbolAddress((void**)&X2,  g_X2);
    cudaGetSymbolAddress((void**)&W2,  g_W2);
    cudaGetSymbolAddress((void**)&Pt,  g_Pt);
    cudaGetSymbolAddress((void**)&Cs,  g_C);

    k_prep<<<NN, 256>>>(A);
    k_quant<<<NN + FO, 256>>>(X, W);
    // GEMM1: Pt[f, j] = bf16( sum_k X2[j,k] * W2[f,k] )   M=NN, N=FO, K=KW
    k_gemm<<<dim3(NN / TM, 1, 1), 256, SMEM_SZ>>>(X2, W2, KW, KW / KC, nullptr, Pt, 0);
    // GEMM2 (split-K=2): C[z][i,f] = sum_{j in half z} Abf[i,j] * Pt[f,j]
    k_gemm<<<dim3(NN / TM, 1, 2), 256, SMEM_SZ>>>(Abf, Pt, NN, NN / KC / 2, Cs, nullptr, 1);
    // out = dis * (C0 + C1) + b
    k_comb<<<NN, 256>>>(out, b);
}